// round 4
// baseline (speedup 1.0000x reference)
#include <cuda_runtime.h>
#include <stdint.h>

// ============================ problem constants ============================
#define BATCH 8192
#define DIMK  2048
#define UNITS 2048

#define BM 128
#define BN 128
#define KCB 128                  // K bytes per chunk (s8 elements)
#define NCHUNK (DIMK / KCB)      // 16
#define NTHREADS 256             // 8 warps: 4 (m) x 2 (n), warp tile 32x64

#define S8_P1 0x01
#define S8_M1 0xFF

// Scratch sign tensors (device globals; no allocations anywhere)
__device__ int8_t g_a8[(size_t)BATCH * DIMK];   // sign(inputs), [M,K] row-major
__device__ int8_t g_b8[(size_t)UNITS * DIMK];   // sign(kernel), transposed to [N,K]

// ============================ helpers ============================
__device__ __forceinline__ uint32_t smem_u32(const void* p) {
    uint32_t a;
    asm("{ .reg .u64 t; cvta.to.shared.u64 t, %1; cvt.u32.u64 %0, t; }" : "=r"(a) : "l"(p));
    return a;
}
__device__ __forceinline__ void cp16(uint32_t saddr, const void* gaddr) {
    asm volatile("cp.async.cg.shared.global [%0], [%1], 16;" :: "r"(saddr), "l"(gaddr));
}
__device__ __forceinline__ void cp_commit() {
    asm volatile("cp.async.commit_group;" ::: "memory");
}
template <int N>
__device__ __forceinline__ void cp_wait() {
    asm volatile("cp.async.wait_group %0;" :: "n"(N) : "memory");
}
__device__ __forceinline__ void ldm_x4(uint32_t* r, uint32_t addr) {
    asm volatile("ldmatrix.sync.aligned.m8n8.x4.shared.b16 {%0,%1,%2,%3}, [%4];"
                 : "=r"(r[0]), "=r"(r[1]), "=r"(r[2]), "=r"(r[3]) : "r"(addr));
}
__device__ __forceinline__ void imma(int* c, const uint32_t* a, uint32_t b0, uint32_t b1) {
    asm volatile(
        "mma.sync.aligned.m16n8k32.row.col.s32.s8.s8.s32 "
        "{%0,%1,%2,%3}, {%4,%5,%6,%7}, {%8,%9}, {%0,%1,%2,%3};"
        : "+r"(c[0]), "+r"(c[1]), "+r"(c[2]), "+r"(c[3])
        : "r"(a[0]), "r"(a[1]), "r"(a[2]), "r"(a[3]), "r"(b0), "r"(b1));
}

// ============================ pack kernels ============================
// inputs [BATCH, DIMK] f32 -> g_a8 s8 signs, same layout. float4 per thread.
__global__ void pack_a_kernel(const float4* __restrict__ x) {
    size_t i = (size_t)blockIdx.x * blockDim.x + threadIdx.x;
    float4 v = x[i];
    uchar4 o;
    o.x = v.x >= 0.0f ? S8_P1 : S8_M1;
    o.y = v.y >= 0.0f ? S8_P1 : S8_M1;
    o.z = v.z >= 0.0f ? S8_P1 : S8_M1;
    o.w = v.w >= 0.0f ? S8_P1 : S8_M1;
    ((uchar4*)g_a8)[i] = o;
}

// kernel [DIMK, UNITS] f32 -> g_b8 s8 signs transposed to [UNITS, DIMK].
__global__ void pack_b_kernel(const float* __restrict__ k) {
    __shared__ uint8_t t[32][33];
    const int n0 = blockIdx.x * 32;
    const int k0 = blockIdx.y * 32;
    const int tx = threadIdx.x, ty = threadIdx.y;
#pragma unroll
    for (int j = ty; j < 32; j += 8) {
        float v = k[(size_t)(k0 + j) * UNITS + n0 + tx];
        t[j][tx] = v >= 0.0f ? S8_P1 : S8_M1;
    }
    __syncthreads();
#pragma unroll
    for (int j = ty; j < 32; j += 8) {
        g_b8[(size_t)(n0 + j) * DIMK + k0 + tx] = (int8_t)t[tx][j];
    }
}

// ============================ IMMA GEMM ============================
// Smem tile layout: 128 rows x 128 bytes, SW128 swizzle at 16B granularity:
//   addr(r, g16) = r*128 + ((g16 ^ (r & 7)) << 4)
// Conflict-free for both the 16B cp.async stores and ldmatrix 8-row reads.
extern __shared__ __align__(128) char sm[];

__global__ void __launch_bounds__(NTHREADS)
bgemm_kernel(const float* __restrict__ bias, float* __restrict__ out) {
    const int tid  = threadIdx.x;
    const int wid  = tid >> 5;
    const int lane = tid & 31;
    const int wm   = wid >> 1;          // 0..3, 32 rows each
    const int wn   = wid & 1;           // 0..1, 64 cols each
    const int row0 = blockIdx.y * BM;
    const int col0 = blockIdx.x * BN;

    const uint32_t sbase = smem_u32(sm);
    const uint32_t OFF_A[2] = {1024u, 1024u + 32768u};
    const uint32_t OFF_B[2] = {1024u + 16384u, 1024u + 49152u};
    float* bs = (float*)sm;             // 128 bias floats at offset 0

    if (tid < BN) bs[tid] = bias[col0 + tid];

    // cooperative async tile loader: 1024 x 16B for A and B each
    const int lr = tid >> 1;            // preconvert per-thread constants
    const int li = (tid & 1) << 2;      // granule base: threads alternate g 0-3 / 4-7

    auto load_tile = [&](int it, int s) {
#pragma unroll
        for (int j = 0; j < 4; ++j) {
            const int r = (lr + j * 128) & 127;       // j covers granule splits
            const int gq = li + j;                     // not used; recompute below
            (void)gq;
        }
        // straightforward mapping: id = tid + 256*j -> r = id>>3, g16 = id&7
#pragma unroll
        for (int j = 0; j < 4; ++j) {
            const int id = tid + NTHREADS * j;
            const int r = id >> 3;
            const int g = id & 7;
            const uint32_t sw = (uint32_t)(r * 128 + ((g ^ (r & 7)) << 4));
            cp16(sbase + OFF_A[s] + sw,
                 g_a8 + (size_t)(row0 + r) * DIMK + it * KCB + g * 16);
            cp16(sbase + OFF_B[s] + sw,
                 g_b8 + (size_t)(col0 + r) * DIMK + it * KCB + g * 16);
        }
        cp_commit();
    };

    int acc[2][8][4];
#pragma unroll
    for (int mt = 0; mt < 2; ++mt)
#pragma unroll
        for (int nt = 0; nt < 8; ++nt)
#pragma unroll
            for (int c = 0; c < 4; ++c) acc[mt][nt][c] = 0;

    // per-thread ldmatrix row/granule constants
    const int a_row = wm * 32 + (lane & 15);          // + mt*16
    const int a_gsel = (lane >> 4);                   // 0/1 -> +16B
    const int b_row = wn * 64 + ((lane >> 4) << 3) + (lane & 7);   // + ntp*16
    const int b_gsel = (lane >> 3) & 1;

    load_tile(0, 0);

    for (int it = 0; it < NCHUNK; ++it) {
        const int s = it & 1;
        if (it + 1 < NCHUNK) {
            load_tile(it + 1, (it + 1) & 1);
            cp_wait<1>();
        } else {
            cp_wait<0>();
        }
        __syncthreads();

        const uint32_t abase = sbase + OFF_A[s];
        const uint32_t bbase = sbase + OFF_B[s];

#pragma unroll
        for (int ks = 0; ks < 4; ++ks) {
            uint32_t afrag[2][4];
#pragma unroll
            for (int mt = 0; mt < 2; ++mt) {
                const int r = a_row + mt * 16;
                const int g16 = ks * 2 + a_gsel;
                ldm_x4(afrag[mt], abase + r * 128 + ((g16 ^ (r & 7)) << 4));
            }
#pragma unroll
            for (int ntp = 0; ntp < 4; ++ntp) {
                const int n = b_row + ntp * 16;
                const int g16 = ks * 2 + b_gsel;
                uint32_t bfrag[4];
                ldm_x4(bfrag, bbase + n * 128 + ((g16 ^ (n & 7)) << 4));
#pragma unroll
                for (int mt = 0; mt < 2; ++mt) {
                    imma(acc[mt][ntp * 2 + 0], afrag[mt], bfrag[0], bfrag[1]);
                    imma(acc[mt][ntp * 2 + 1], afrag[mt], bfrag[2], bfrag[3]);
                }
            }
        }
        __syncthreads();
    }

    // epilogue: s32 -> f32 + bias, float2 stores
    const int g = lane >> 2;
    const int cq = (lane & 3) * 2;
#pragma unroll
    for (int mt = 0; mt < 2; ++mt) {
        const int r0 = row0 + wm * 32 + mt * 16 + g;
#pragma unroll
        for (int nt = 0; nt < 8; ++nt) {
            const int cl = wn * 64 + nt * 8 + cq;     // col within CTA tile
            const float b0 = bs[cl], b1 = bs[cl + 1];
            float2 v0, v1;
            v0.x = (float)acc[mt][nt][0] + b0;
            v0.y = (float)acc[mt][nt][1] + b1;
            v1.x = (float)acc[mt][nt][2] + b0;
            v1.y = (float)acc[mt][nt][3] + b1;
            *(float2*)(out + (size_t)r0 * UNITS + col0 + cl) = v0;
            *(float2*)(out + (size_t)(r0 + 8) * UNITS + col0 + cl) = v1;
        }
    }
}

// ============================ harness entry ============================
extern "C" void kernel_launch(void* const* d_in, const int* in_sizes, int n_in,
                              void* d_out, int out_size) {
    (void)in_sizes; (void)n_in; (void)out_size;
    const float* x    = (const float*)d_in[0];
    const float* k    = (const float*)d_in[1];
    const float* bias = (const float*)d_in[2];
    float* out        = (float*)d_out;

    const int SMEM_BYTES = 1024 + 4 * 16384;          // 66560
    cudaFuncSetAttribute(bgemm_kernel, cudaFuncAttributeMaxDynamicSharedMemorySize,
                         SMEM_BYTES);

    pack_a_kernel<<<(BATCH * DIMK / 4) / 256, 256>>>((const float4*)x);
    pack_b_kernel<<<dim3(UNITS / 32, DIMK / 32), dim3(32, 8)>>>(k);
    bgemm_kernel<<<dim3(UNITS / BN, BATCH / BM), NTHREADS, SMEM_BYTES>>>(bias, out);
}

// round 5
// speedup vs baseline: 1.8686x; 1.8686x over previous
#include <cuda_runtime.h>
#include <stdint.h>

// ============================ problem constants ============================
#define BATCH 8192
#define DIMK  2048
#define UNITS 2048
#define KW    (DIMK / 32)        // 64 packed 32-bit words along K

#define BM 128
#define BN 128
#define NT 256                   // 8 warps

// Packed sign bits (bit = 1 iff value >= 0)
__device__ uint32_t g_xbits[(size_t)BATCH * KW];   // [row][w]   2 MB
__device__ uint32_t g_kbits[(size_t)UNITS * KW];   // [unit][w]  0.5 MB

// ---------------------------------------------------------------------------
// pack_x: each warp packs 256 consecutive floats -> 8 words.
// 8 coalesced 128B loads per warp (MLP=8), ballot preserves bit order:
// word (warp*8+k) bit j = sign(x[warp*256 + k*32 + j]).
// ---------------------------------------------------------------------------
__global__ void pack_x_kernel(const float* __restrict__ x) {
    const int warp = blockIdx.x * (NT / 32) + (threadIdx.x >> 5);
    const int lane = threadIdx.x & 31;
    const float* p = x + (size_t)warp * 256;
    const size_t wbase = (size_t)warp * 8;
#pragma unroll
    for (int k = 0; k < 8; ++k) {
        float v = p[k * 32 + lane];
        unsigned m = __ballot_sync(0xffffffffu, v >= 0.0f);
        if (lane == k) g_xbits[wbase + k] = m;
    }
}

// ---------------------------------------------------------------------------
// pack_k: kernel [DIMK, UNITS] f32 -> per-unit bit columns g_kbits[n*KW + w],
// bit j of word w = sign(kernel[(w*32+j)*UNITS + n]). Coalesced across n.
// ---------------------------------------------------------------------------
__global__ void pack_k_kernel(const float* __restrict__ k) {
    const int w = blockIdx.x;
    const int n = blockIdx.y * blockDim.x + threadIdx.x;
    const float* col = k + (size_t)w * 32 * UNITS + n;
    uint32_t bits = 0;
#pragma unroll
    for (int j = 0; j < 32; ++j) {
        bits |= (col[(size_t)j * UNITS] >= 0.0f ? 1u : 0u) << j;
    }
    g_kbits[(size_t)n * KW + w] = bits;
}

// ---------------------------------------------------------------------------
// Binary GEMM: out[r][c] = DIM - 2*popc(xrow ^ kcol) + bias[c]
//
// BM=BN=128, 256 threads, 8x8 outputs per thread at rows (tm + 16*i),
// cols (tn + 16*j); tm = tid>>4, tn = tid&15 (interleaved stride-16 keeps
// shared reads conflict-free under the XOR swizzle).
//
// Shared tiles word-major with XOR swizzle on low 5 bits of the row index:
// element (w, r) at [w*128 + (r ^ (w & 31))].
//  - Loader: lanes = consecutive w, fixed r  -> distinct banks.
//  - Compute A: 2 addresses/warp (differ in bit0) -> broadcast, no conflict.
//  - Compute B: 16 distinct banks + tm-pair broadcast -> no conflict.
//
// K unrolled by 2: acc += popc(p0) + popc(p1) maps to one IADD3.
// ---------------------------------------------------------------------------
extern __shared__ uint32_t smw[];   // sa[64*128] then sb[64*128] = 64 KB

__global__ void __launch_bounds__(NT)
bgemm_kernel(const float* __restrict__ bias, float* __restrict__ out) {
    uint32_t* sa = smw;
    uint32_t* sb = smw + KW * BM;

    const int tid  = threadIdx.x;
    const int row0 = blockIdx.y * BM;
    const int col0 = blockIdx.x * BN;

    // Cooperative load of both 64x128-word tiles (whole K dimension).
    {
        const int w  = tid & 63;
        const int r0 = tid >> 6;          // 0..3
        const int s  = w & 31;
        const uint32_t* ga = g_xbits + (size_t)row0 * KW + w;
        const uint32_t* gb = g_kbits + (size_t)col0 * KW + w;
#pragma unroll
        for (int it = 0; it < 32; ++it) {
            const int r = r0 + it * 4;
            sa[w * BM + (r ^ s)] = ga[(size_t)r * KW];
            sb[w * BN + (r ^ s)] = gb[(size_t)r * KW];
        }
    }
    __syncthreads();

    const int tm = tid >> 4;   // 0..15
    const int tn = tid & 15;   // 0..15

    int acc[8][8];
#pragma unroll
    for (int i = 0; i < 8; ++i)
#pragma unroll
        for (int j = 0; j < 8; ++j) acc[i][j] = 0;

#pragma unroll 1
    for (int w = 0; w < KW; w += 2) {
        const int s0 = w & 31;
        const int s1 = (w + 1) & 31;
        uint32_t a0[8], a1[8], b0[8], b1[8];
#pragma unroll
        for (int i = 0; i < 8; ++i) {
            a0[i] = sa[w * BM + ((tm + 16 * i) ^ s0)];
            a1[i] = sa[(w + 1) * BM + ((tm + 16 * i) ^ s1)];
        }
#pragma unroll
        for (int j = 0; j < 8; ++j) {
            b0[j] = sb[w * BN + ((tn + 16 * j) ^ s0)];
            b1[j] = sb[(w + 1) * BN + ((tn + 16 * j) ^ s1)];
        }
#pragma unroll
        for (int i = 0; i < 8; ++i)
#pragma unroll
            for (int j = 0; j < 8; ++j)
                acc[i][j] += __popc(a0[i] ^ b0[j]) + __popc(a1[i] ^ b1[j]);
    }

    // Epilogue: out = DIM - 2*acc + bias. Per-warp stores cover 2 rows x 16
    // consecutive cols per instruction (two full 64B sectors).
    float bv[8];
#pragma unroll
    for (int j = 0; j < 8; ++j) bv[j] = bias[col0 + tn + 16 * j];

#pragma unroll
    for (int i = 0; i < 8; ++i) {
        float* orow = out + (size_t)(row0 + tm + 16 * i) * UNITS + col0;
#pragma unroll
        for (int j = 0; j < 8; ++j) {
            orow[tn + 16 * j] = (float)(DIMK - 2 * acc[i][j]) + bv[j];
        }
    }
}

// ============================ harness entry ============================
extern "C" void kernel_launch(void* const* d_in, const int* in_sizes, int n_in,
                              void* d_out, int out_size) {
    (void)in_sizes; (void)n_in; (void)out_size;
    const float* x    = (const float*)d_in[0];
    const float* k    = (const float*)d_in[1];
    const float* bias = (const float*)d_in[2];
    float* out        = (float*)d_out;

    const int SMEM_BYTES = 2 * KW * BM * 4;          // 65536
    cudaFuncSetAttribute(bgemm_kernel, cudaFuncAttributeMaxDynamicSharedMemorySize,
                         SMEM_BYTES);

    // pack_x: one warp per 256 floats -> 8192 blocks of 256 threads
    pack_x_kernel<<<(BATCH * DIMK) / (256 * (NT / 32)), NT>>>(x);
    pack_k_kernel<<<dim3(KW, UNITS / 256), 256>>>(k);
    bgemm_kernel<<<dim3(UNITS / BN, BATCH / BM), NT, SMEM_BYTES>>>(bias, out);
}